// round 13
// baseline (speedup 1.0000x reference)
#include <cuda_runtime.h>
#include <math.h>

#define SEQ     16384
#define IN_DIM  512
#define HID     1024
#define OUT_DIM 256

#define NB      128     // scan blocks (<148 SMs => all co-resident)
#define SCAN_T  256     // 8 warps, one hidden row per warp

// ---- scratch (static __device__; no allocs anywhere) ----
__device__ float    g_xh[SEQ * HID];      // 64 MB  xh = input@Wxh.T + bias
__device__ float    g_outs[SEQ * HID];    // 64 MB  h_1..h_SEQ for GEMM3
__device__ unsigned g_hx[2][HID];         // tagged h exchange (tag = low 2 bits)
__device__ float    g_bias[HID];          // Wxh_b + Whh_b + bh

// morally-strong relaxed ops (R4/R9/R10/R11-proven mechanism)
__device__ __forceinline__ void st_relaxed_v4(unsigned* p, uint4 v) {
    asm volatile("st.relaxed.gpu.global.v4.u32 [%0], {%1,%2,%3,%4};"
                 :: "l"(p), "r"(v.x), "r"(v.y), "r"(v.z), "r"(v.w) : "memory");
}
__device__ __forceinline__ uint4 ld_relaxed_v4(const unsigned* p) {
    uint4 v;
    asm volatile("ld.relaxed.gpu.global.v4.u32 {%0,%1,%2,%3}, [%4];"
                 : "=r"(v.x), "=r"(v.y), "=r"(v.z), "=r"(v.w)
                 : "l"(p) : "memory");
    return v;
}

#define TAGOK(u, tg) ((((u).x & 3u) == (tg)) & (((u).y & 3u) == (tg)) & \
                      (((u).z & 3u) == (tg)) & (((u).w & 3u) == (tg)))

// branch-free tanh: 1 - 2/(1+e^{2x}); MUFU-only, abs err ~1e-7, inf-safe.
__device__ __forceinline__ float fast_tanh(float x) {
    float t = __expf(2.0f * x);
    return 1.0f - __fdividef(2.0f, 1.0f + t);
}

// ---------------------------------------------------------------- reset ----
__global__ void reset_kernel(const float* __restrict__ hidden,
                             const float* __restrict__ wxb,
                             const float* __restrict__ whb,
                             const float* __restrict__ bh) {
    int i = threadIdx.x;  // 1024 threads
    g_bias[i] = wxb[i] + whb[i] + bh[i];
    // slot 0 = h_0 with tag 0 (consumed at iter 0)
    g_hx[0][i] = (__float_as_uint(hidden[i]) & ~3u) | 0u;
    // slot 1 prefill: tag 2 (never matches iter-1's expected tag 1)
    g_hx[1][i] = 2u;
}

// --------------------------------------------------- generic NT fp32 GEMM --
// C[m][n] = sum_k A[m][k] * B[n][k] + bias[n]
__global__ void gemm_nt_bias(const float* __restrict__ A,
                             const float* __restrict__ B,
                             const float* __restrict__ bias,
                             float* __restrict__ C,
                             int M, int N, int K) {
    __shared__ float As[16][65];
    __shared__ float Bs[16][65];
    const int tid = threadIdx.x;
    const int bx = blockIdx.x;
    const int by = blockIdx.y;
    const int tm = (tid >> 4) << 2;
    const int tn = (tid & 15) << 2;
    const int lr = tid >> 2;
    const int lk = (tid & 3) << 2;

    const float* Ap = A + (size_t)(by * 64 + lr) * K + lk;
    const float* Bp = B + (size_t)(bx * 64 + lr) * K + lk;

    float acc[4][4] = {};

    for (int k0 = 0; k0 < K; k0 += 16) {
        float4 av = *(const float4*)(Ap + k0);
        float4 bv = *(const float4*)(Bp + k0);
        As[lk + 0][lr] = av.x; As[lk + 1][lr] = av.y;
        As[lk + 2][lr] = av.z; As[lk + 3][lr] = av.w;
        Bs[lk + 0][lr] = bv.x; Bs[lk + 1][lr] = bv.y;
        Bs[lk + 2][lr] = bv.z; Bs[lk + 3][lr] = bv.w;
        __syncthreads();
#pragma unroll
        for (int k = 0; k < 16; k++) {
            float ra[4], rb[4];
#pragma unroll
            for (int i = 0; i < 4; i++) ra[i] = As[k][tm + i];
#pragma unroll
            for (int j = 0; j < 4; j++) rb[j] = Bs[k][tn + j];
#pragma unroll
            for (int i = 0; i < 4; i++)
#pragma unroll
                for (int j = 0; j < 4; j++)
                    acc[i][j] += ra[i] * rb[j];
        }
        __syncthreads();
    }

    float bb[4];
#pragma unroll
    for (int j = 0; j < 4; j++) bb[j] = bias[bx * 64 + tn + j];
#pragma unroll
    for (int i = 0; i < 4; i++) {
        int row = by * 64 + tm + i;
        float* cp = C + (size_t)row * N + bx * 64 + tn;
#pragma unroll
        for (int j = 0; j < 4; j++) cp[j] = acc[i][j] + bb[j];
    }
}

// ------ tagged-staging persistent scan with PIPELINED (depth-3) polling ----
// Identical to the R11 winner (dense exchange, aggregated 16B publishes,
// 2-bit mantissa tags) except the poll keeps 3 loads in flight so memory is
// sampled every ~RTT/3 cycles instead of once per RTT, removing the
// detection-quantization tail that gates each step.
__global__ void __launch_bounds__(SCAN_T, 1)
scan_kernel(const float* __restrict__ Whh) {
    const int bid  = blockIdx.x;
    const int tid  = threadIdx.x;
    const int wid  = tid >> 5;
    const int lane = tid & 31;
    const int row  = bid * 8 + wid;          // my warp's hidden row

    // Whh row slice in registers: w4[k] = Whh[row][k*128 + lane*4 .. +3]
    float4 w4[8];
#pragma unroll
    for (int k = 0; k < 8; k++)
        w4[k] = *(const float4*)&Whh[(size_t)row * HID + k * 128 + lane * 4];

    __shared__ float    hs[HID];
    __shared__ unsigned hout[8];             // tagged h_{t+1} of this block

    // xh pipeline (lane 0 of each warp), depth 2
    float xh_c = 0.f, xh_n = 0.f;
    if (lane == 0) {
        xh_c = g_xh[row];
        xh_n = g_xh[(size_t)HID + row];
    }

#pragma unroll 1
    for (int t = 0; t < SEQ; t++) {
        // ---- fused poll+stage with 3 in-flight samples ----
        {
            const unsigned* p = g_hx[t & 1] + tid * 4;
            const unsigned  tg = (unsigned)(t & 3);
            uint4 u = ld_relaxed_v4(p);
            if (!TAGOK(u, tg)) {
                uint4 b = ld_relaxed_v4(p);
                uint4 c = ld_relaxed_v4(p);
                for (;;) {
                    if (TAGOK(u, tg)) break;
                    u = b; b = c; c = ld_relaxed_v4(p);
                }
            }
            *(uint4*)&((unsigned*)hs)[tid * 4] = u;
        }
        __syncthreads();

        // ---- MV: acc = Whh[row] . h_t  (8 x LDS.128) ----
        float a0 = 0.f, a1 = 0.f, a2 = 0.f, a3 = 0.f;
#pragma unroll
        for (int k = 0; k < 8; k++) {
            float4 hv = *(const float4*)&hs[k * 128 + lane * 4];
            a0 = fmaf(w4[k].x, hv.x, a0);
            a1 = fmaf(w4[k].y, hv.y, a1);
            a2 = fmaf(w4[k].z, hv.z, a2);
            a3 = fmaf(w4[k].w, hv.w, a3);
        }
        float acc = (a0 + a1) + (a2 + a3);
#pragma unroll
        for (int o = 16; o > 0; o >>= 1)
            acc += __shfl_xor_sync(0xFFFFFFFFu, acc, o);

        if (lane == 0) {
            float hn = fast_tanh(xh_c + acc);
            unsigned nb = (__float_as_uint(hn) & ~3u) |
                          (unsigned)((t + 1) & 3);
            hout[wid] = nb;                               // stage for publish
            g_outs[(size_t)t * HID + row] = __uint_as_float(nb);
            xh_c = xh_n;
            xh_n = (t + 2 < SEQ) ? __ldg(&g_xh[(size_t)(t + 2) * HID + row])
                                 : 0.f;
        }
        __syncthreads();       // hout complete; hs fully consumed

        // ---- aggregated publish: two 16B stores cover the block's 8 rows --
        if (tid < 2)
            st_relaxed_v4(&g_hx[(t + 1) & 1][bid * 8 + tid * 4],
                          *(const uint4*)&hout[tid * 4]);
    }
}

// ----------------------------------------------------------- row softmax ---
__global__ void softmax256(float* __restrict__ X) {
    const int r = blockIdx.x;
    const int tid = threadIdx.x;          // 256
    const int wid = tid >> 5, lane = tid & 31;
    __shared__ float red[8];

    float v = X[(size_t)r * OUT_DIM + tid];

    float m = v;
#pragma unroll
    for (int o = 16; o > 0; o >>= 1)
        m = fmaxf(m, __shfl_xor_sync(0xFFFFFFFFu, m, o));
    if (lane == 0) red[wid] = m;
    __syncthreads();
    if (tid == 0) {
        float mm = red[0];
#pragma unroll
        for (int i = 1; i < 8; i++) mm = fmaxf(mm, red[i]);
        red[0] = mm;
    }
    __syncthreads();
    const float bm = red[0];
    __syncthreads();

    float e = expf(v - bm);
    float s = e;
#pragma unroll
    for (int o = 16; o > 0; o >>= 1)
        s += __shfl_xor_sync(0xFFFFFFFFu, s, o);
    if (lane == 0) red[wid] = s;
    __syncthreads();
    if (tid == 0) {
        float ss = red[0];
#pragma unroll
        for (int i = 1; i < 8; i++) ss += red[i];
        red[0] = ss;
    }
    __syncthreads();
    X[(size_t)r * OUT_DIM + tid] = e / red[0];
}

// ------------------------------------------------------------------ launch -
extern "C" void kernel_launch(void* const* d_in, const int* in_sizes, int n_in,
                              void* d_out, int out_size) {
    const float* input  = (const float*)d_in[0];   // (SEQ, IN)
    const float* hidden = (const float*)d_in[1];   // (HID,)
    const float* Wxh_w  = (const float*)d_in[2];   // (HID, IN)
    const float* Wxh_b  = (const float*)d_in[3];   // (HID,)
    const float* Whh_w  = (const float*)d_in[4];   // (HID, HID)
    const float* Whh_b  = (const float*)d_in[5];   // (HID,)
    const float* bh     = (const float*)d_in[6];   // (HID,)
    const float* fc_w   = (const float*)d_in[7];   // (OUT, HID)
    const float* fc_b   = (const float*)d_in[8];   // (OUT,)
    float* out = (float*)d_out;                    // (SEQ, OUT)

    float* xh_ptr   = nullptr;
    float* outs_ptr = nullptr;
    float* bias_ptr = nullptr;
    cudaGetSymbolAddress((void**)&xh_ptr,   g_xh);
    cudaGetSymbolAddress((void**)&outs_ptr, g_outs);
    cudaGetSymbolAddress((void**)&bias_ptr, g_bias);

    // 0) fold biases + seed tagged exchange slots (every launch => replay-safe)
    reset_kernel<<<1, HID>>>(hidden, Wxh_b, Whh_b, bh);

    // 1) xh = input @ Wxh.T + bias        (M=SEQ, N=HID, K=IN)
    {
        dim3 grid(HID / 64, SEQ / 64);
        gemm_nt_bias<<<grid, 256>>>(input, Wxh_w, bias_ptr, xh_ptr,
                                    SEQ, HID, IN_DIM);
    }

    // 2) sequential recurrence (tagged-staging, pipelined polls)
    scan_kernel<<<NB, SCAN_T>>>(Whh_w);

    // 3) logits = outs @ fc_w.T + fc_b    (M=SEQ, N=OUT, K=HID) -> d_out
    {
        dim3 grid(OUT_DIM / 64, SEQ / 64);
        gemm_nt_bias<<<grid, 256>>>(outs_ptr, fc_w, fc_b, out,
                                    SEQ, OUT_DIM, HID);
    }

    // 4) softmax rows in place on d_out
    softmax256<<<SEQ, OUT_DIM>>>(out);
}

// round 15
// speedup vs baseline: 1.1276x; 1.1276x over previous
#include <cuda_runtime.h>
#include <math.h>

#define SEQ     16384
#define IN_DIM  512
#define HID     1024
#define OUT_DIM 256

#define NB      128     // scan blocks (<148 SMs => all co-resident)
#define SCAN_T  256     // 8 warps, one hidden row per warp

// ---- scratch (static __device__; no allocs anywhere) ----
__device__ float    g_xh[SEQ * HID];      // 64 MB  xh = input@Wxh.T + bias
__device__ float    g_outs[SEQ * HID];    // 64 MB  h_1..h_SEQ for GEMM3
__device__ unsigned g_hx[2][HID];         // tagged h exchange (tag = low 2 bits)
__device__ float    g_bias[HID];          // Wxh_b + Whh_b + bh

// morally-strong relaxed ops (R4/R9/R10/R11-proven mechanism)
__device__ __forceinline__ void st_relaxed_v4(unsigned* p, uint4 v) {
    asm volatile("st.relaxed.gpu.global.v4.u32 [%0], {%1,%2,%3,%4};"
                 :: "l"(p), "r"(v.x), "r"(v.y), "r"(v.z), "r"(v.w) : "memory");
}
__device__ __forceinline__ uint4 ld_relaxed_v4(const unsigned* p) {
    uint4 v;
    asm volatile("ld.relaxed.gpu.global.v4.u32 {%0,%1,%2,%3}, [%4];"
                 : "=r"(v.x), "=r"(v.y), "=r"(v.z), "=r"(v.w)
                 : "l"(p) : "memory");
    return v;
}

#define TAGOK(u, tg) ((((u).x & 3u) == (tg)) & (((u).y & 3u) == (tg)) & \
                      (((u).z & 3u) == (tg)) & (((u).w & 3u) == (tg)))

// branch-free tanh: 1 - 2/(1+e^{2x}); MUFU-only, abs err ~1e-7, inf-safe.
__device__ __forceinline__ float fast_tanh(float x) {
    float t = __expf(2.0f * x);
    return 1.0f - __fdividef(2.0f, 1.0f + t);
}

// ---------------------------------------------------------------- reset ----
__global__ void reset_kernel(const float* __restrict__ hidden,
                             const float* __restrict__ wxb,
                             const float* __restrict__ whb,
                             const float* __restrict__ bh) {
    int i = threadIdx.x;  // 1024 threads
    g_bias[i] = wxb[i] + whb[i] + bh[i];
    // slot 0 = h_0 with tag 0 (consumed at iter 0)
    g_hx[0][i] = (__float_as_uint(hidden[i]) & ~3u) | 0u;
    // slot 1 prefill: tag 2 (never matches iter-1's expected tag 1)
    g_hx[1][i] = 2u;
}

// --------------------------------------------------- generic NT fp32 GEMM --
// C[m][n] = sum_k A[m][k] * B[n][k] + bias[n]
__global__ void gemm_nt_bias(const float* __restrict__ A,
                             const float* __restrict__ B,
                             const float* __restrict__ bias,
                             float* __restrict__ C,
                             int M, int N, int K) {
    __shared__ float As[16][65];
    __shared__ float Bs[16][65];
    const int tid = threadIdx.x;
    const int bx = blockIdx.x;
    const int by = blockIdx.y;
    const int tm = (tid >> 4) << 2;
    const int tn = (tid & 15) << 2;
    const int lr = tid >> 2;
    const int lk = (tid & 3) << 2;

    const float* Ap = A + (size_t)(by * 64 + lr) * K + lk;
    const float* Bp = B + (size_t)(bx * 64 + lr) * K + lk;

    float acc[4][4] = {};

    for (int k0 = 0; k0 < K; k0 += 16) {
        float4 av = *(const float4*)(Ap + k0);
        float4 bv = *(const float4*)(Bp + k0);
        As[lk + 0][lr] = av.x; As[lk + 1][lr] = av.y;
        As[lk + 2][lr] = av.z; As[lk + 3][lr] = av.w;
        Bs[lk + 0][lr] = bv.x; Bs[lk + 1][lr] = bv.y;
        Bs[lk + 2][lr] = bv.z; Bs[lk + 3][lr] = bv.w;
        __syncthreads();
#pragma unroll
        for (int k = 0; k < 16; k++) {
            float ra[4], rb[4];
#pragma unroll
            for (int i = 0; i < 4; i++) ra[i] = As[k][tm + i];
#pragma unroll
            for (int j = 0; j < 4; j++) rb[j] = Bs[k][tn + j];
#pragma unroll
            for (int i = 0; i < 4; i++)
#pragma unroll
                for (int j = 0; j < 4; j++)
                    acc[i][j] += ra[i] * rb[j];
        }
        __syncthreads();
    }

    float bb[4];
#pragma unroll
    for (int j = 0; j < 4; j++) bb[j] = bias[bx * 64 + tn + j];
#pragma unroll
    for (int i = 0; i < 4; i++) {
        int row = by * 64 + tm + i;
        float* cp = C + (size_t)row * N + bx * 64 + tn;
#pragma unroll
        for (int j = 0; j < 4; j++) cp[j] = acc[i][j] + bb[j];
    }
}

// --- tagged-staging scan: 1 sync/step, last-warp publish, spec next-slot ---
// R11 protocol (dense tagged exchange, aggregated 16B publishes) with:
//  * hs double-buffered -> second __syncthreads removed
//  * publish fired by the LAST warp to finish (smem arrival counter), not
//    after a block barrier
//  * one speculative sample of the next slot issued during the compute
//    window; checked before polling next iteration
__global__ void __launch_bounds__(SCAN_T, 1)
scan_kernel(const float* __restrict__ Whh) {
    const int bid  = blockIdx.x;
    const int tid  = threadIdx.x;
    const int wid  = tid >> 5;
    const int lane = tid & 31;
    const int row  = bid * 8 + wid;          // my warp's hidden row

    // Whh row slice in registers: w4[k] = Whh[row][k*128 + lane*4 .. +3]
    float4 w4[8];
#pragma unroll
    for (int k = 0; k < 8; k++)
        w4[k] = *(const float4*)&Whh[(size_t)row * HID + k * 128 + lane * 4];

    __shared__ float    hs[2][HID];          // double-buffered staged h
    __shared__ unsigned hout[8];             // tagged h_{t+1} of this block
    __shared__ unsigned scnt;                // warp arrival counter

    if (tid == 0) scnt = 0u;
    __syncthreads();

    // xh pipeline (lane 0 of each warp), depth 2
    float xh_c = 0.f, xh_n = 0.f;
    if (lane == 0) {
        xh_c = g_xh[row];
        xh_n = g_xh[(size_t)HID + row];
    }

    uint4 spec = make_uint4(3u, 3u, 3u, 3u);   // invalid tag for iter 0

#pragma unroll 1
    for (int t = 0; t < SEQ; t++) {
        // ---- fused poll+stage (check speculative sample first) ----
        {
            const unsigned* p = g_hx[t & 1] + tid * 4;
            const unsigned  tg = (unsigned)(t & 3);
            uint4 u = spec;
            if (!TAGOK(u, tg)) {
                u = ld_relaxed_v4(p);
                while (!TAGOK(u, tg))
                    u = ld_relaxed_v4(p);
            }
            *(uint4*)&((unsigned*)hs[t & 1])[tid * 4] = u;
        }
        // speculative sample of next slot (consumed at iter t+1)
        spec = ld_relaxed_v4(g_hx[(t + 1) & 1] + tid * 4);
        __syncthreads();                         // hs[t&1] fully staged

        // ---- MV: acc = Whh[row] . h_t  (8 x LDS.128) ----
        const float* hb = hs[t & 1];
        float a0 = 0.f, a1 = 0.f, a2 = 0.f, a3 = 0.f;
#pragma unroll
        for (int k = 0; k < 8; k++) {
            float4 hv = *(const float4*)&hb[k * 128 + lane * 4];
            a0 = fmaf(w4[k].x, hv.x, a0);
            a1 = fmaf(w4[k].y, hv.y, a1);
            a2 = fmaf(w4[k].z, hv.z, a2);
            a3 = fmaf(w4[k].w, hv.w, a3);
        }
        float acc = (a0 + a1) + (a2 + a3);
#pragma unroll
        for (int o = 16; o > 0; o >>= 1)
            acc += __shfl_xor_sync(0xFFFFFFFFu, acc, o);

        if (lane == 0) {
            float hn = fast_tanh(xh_c + acc);
            unsigned nb = (__float_as_uint(hn) & ~3u) |
                          (unsigned)((t + 1) & 3);
            hout[wid] = nb;
            __threadfence_block();
            unsigned old = atomicAdd(&scnt, 1u);
            if (old == (unsigned)(8 * t + 7)) {
                // last warp: publish the block's 8 rows as two 16B stores
                __threadfence_block();
                const volatile unsigned* hv = hout;
                uint4 lo = make_uint4(hv[0], hv[1], hv[2], hv[3]);
                uint4 hi = make_uint4(hv[4], hv[5], hv[6], hv[7]);
                st_relaxed_v4(&g_hx[(t + 1) & 1][bid * 8 + 0], lo);
                st_relaxed_v4(&g_hx[(t + 1) & 1][bid * 8 + 4], hi);
            }
            g_outs[(size_t)t * HID + row] = __uint_as_float(nb);
            xh_c = xh_n;
            xh_n = (t + 2 < SEQ) ? __ldg(&g_xh[(size_t)(t + 2) * HID + row])
                                 : 0.f;
        }
        // no second __syncthreads: hs is double-buffered, hout/scnt are
        // ordered by the fence+atomic chain above
    }
}

// ----------------------------------------------------------- row softmax ---
__global__ void softmax256(float* __restrict__ X) {
    const int r = blockIdx.x;
    const int tid = threadIdx.x;          // 256
    const int wid = tid >> 5, lane = tid & 31;
    __shared__ float red[8];

    float v = X[(size_t)r * OUT_DIM + tid];

    float m = v;
#pragma unroll
    for (int o = 16; o > 0; o >>= 1)
        m = fmaxf(m, __shfl_xor_sync(0xFFFFFFFFu, m, o));
    if (lane == 0) red[wid] = m;
    __syncthreads();
    if (tid == 0) {
        float mm = red[0];
#pragma unroll
        for (int i = 1; i < 8; i++) mm = fmaxf(mm, red[i]);
        red[0] = mm;
    }
    __syncthreads();
    const float bm = red[0];
    __syncthreads();

    float e = expf(v - bm);
    float s = e;
#pragma unroll
    for (int o = 16; o > 0; o >>= 1)
        s += __shfl_xor_sync(0xFFFFFFFFu, s, o);
    if (lane == 0) red[wid] = s;
    __syncthreads();
    if (tid == 0) {
        float ss = red[0];
#pragma unroll
        for (int i = 1; i < 8; i++) ss += red[i];
        red[0] = ss;
    }
    __syncthreads();
    X[(size_t)r * OUT_DIM + tid] = e / red[0];
}

// ------------------------------------------------------------------ launch -
extern "C" void kernel_launch(void* const* d_in, const int* in_sizes, int n_in,
                              void* d_out, int out_size) {
    const float* input  = (const float*)d_in[0];   // (SEQ, IN)
    const float* hidden = (const float*)d_in[1];   // (HID,)
    const float* Wxh_w  = (const float*)d_in[2];   // (HID, IN)
    const float* Wxh_b  = (const float*)d_in[3];   // (HID,)
    const float* Whh_w  = (const float*)d_in[4];   // (HID, HID)
    const float* Whh_b  = (const float*)d_in[5];   // (HID,)
    const float* bh     = (const float*)d_in[6];   // (HID,)
    const float* fc_w   = (const float*)d_in[7];   // (OUT, HID)
    const float* fc_b   = (const float*)d_in[8];   // (OUT,)
    float* out = (float*)d_out;                    // (SEQ, OUT)

    float* xh_ptr   = nullptr;
    float* outs_ptr = nullptr;
    float* bias_ptr = nullptr;
    cudaGetSymbolAddress((void**)&xh_ptr,   g_xh);
    cudaGetSymbolAddress((void**)&outs_ptr, g_outs);
    cudaGetSymbolAddress((void**)&bias_ptr, g_bias);

    // 0) fold biases + seed tagged exchange slots (every launch => replay-safe)
    reset_kernel<<<1, HID>>>(hidden, Wxh_b, Whh_b, bh);

    // 1) xh = input @ Wxh.T + bias        (M=SEQ, N=HID, K=IN)
    {
        dim3 grid(HID / 64, SEQ / 64);
        gemm_nt_bias<<<grid, 256>>>(input, Wxh_w, bias_ptr, xh_ptr,
                                    SEQ, HID, IN_DIM);
    }

    // 2) sequential recurrence (tagged-staging, 1 sync/step, spec polls)
    scan_kernel<<<NB, SCAN_T>>>(Whh_w);

    // 3) logits = outs @ fc_w.T + fc_b    (M=SEQ, N=OUT, K=HID) -> d_out
    {
        dim3 grid(OUT_DIM / 64, SEQ / 64);
        gemm_nt_bias<<<grid, 256>>>(outs_ptr, fc_w, fc_b, out,
                                    SEQ, OUT_DIM, HID);
    }

    // 4) softmax rows in place on d_out
    softmax256<<<SEQ, OUT_DIM>>>(out);
}

// round 17
// speedup vs baseline: 1.5598x; 1.3833x over previous
#include <cuda_runtime.h>
#include <math.h>

#define SEQ     16384
#define IN_DIM  512
#define HID     1024
#define OUT_DIM 256

#define NB      128     // scan blocks (<148 SMs => all co-resident)
#define SCAN_T  512     // warps 0-7: scan consumers; warps 8-15: xh producers

// ---- scratch (static __device__; no allocs anywhere) ----
__device__ unsigned g_xh[SEQ * HID];      // 64 MB  tagged xh (tag=1, single-write)
__device__ float    g_outs[SEQ * HID];    // 64 MB  h_1..h_SEQ for GEMM2
__device__ unsigned g_hx[2][HID];         // tagged h exchange (tag = low 2 bits)

// morally-strong relaxed ops (R4/R9/R10/R11-proven; weak ops are UNSAFE here,
// proven by R16's ABA corruption)
__device__ __forceinline__ void st_relaxed_v4(unsigned* p, uint4 v) {
    asm volatile("st.relaxed.gpu.global.v4.u32 [%0], {%1,%2,%3,%4};"
                 :: "l"(p), "r"(v.x), "r"(v.y), "r"(v.z), "r"(v.w) : "memory");
}
__device__ __forceinline__ uint4 ld_relaxed_v4(const unsigned* p) {
    uint4 v;
    asm volatile("ld.relaxed.gpu.global.v4.u32 {%0,%1,%2,%3}, [%4];"
                 : "=r"(v.x), "=r"(v.y), "=r"(v.z), "=r"(v.w)
                 : "l"(p) : "memory");
    return v;
}
__device__ __forceinline__ void st_relaxed_u32(unsigned* p, unsigned v) {
    asm volatile("st.relaxed.gpu.global.u32 [%0], %1;" :: "l"(p), "r"(v) : "memory");
}
__device__ __forceinline__ unsigned ld_relaxed_u32(const unsigned* p) {
    unsigned v;
    asm volatile("ld.relaxed.gpu.global.u32 %0, [%1];" : "=r"(v) : "l"(p) : "memory");
    return v;
}

#define TAGOK(u, tg) ((((u).x & 3u) == (tg)) & (((u).y & 3u) == (tg)) & \
                      (((u).z & 3u) == (tg)) & (((u).w & 3u) == (tg)))

#define BAR_SCAN() asm volatile("bar.sync 1, 256;" ::: "memory")
#define BAR_PROD() asm volatile("bar.sync 2, 256;" ::: "memory")

// branch-free tanh: 1 - 2/(1+e^{2x}); MUFU-only, abs err ~1e-7, inf-safe.
__device__ __forceinline__ float fast_tanh(float x) {
    float t = __expf(2.0f * x);
    return 1.0f - __fdividef(2.0f, 1.0f + t);
}

// xh poll: spin until word carries tag 1 (single-write per launch => no ABA)
__device__ __forceinline__ float poll_xh(const unsigned* p) {
    unsigned w = ld_relaxed_u32(p);
    while ((w & 3u) != 1u) w = ld_relaxed_u32(p);
    return __uint_as_float(w);
}

// ---------------------------------------------------------------- reset ----
__global__ void reset_kernel(const float* __restrict__ hidden) {
    int i = threadIdx.x;  // 1024 threads
    // slot 0 = h_0 with tag 0 (consumed at iter 0)
    g_hx[0][i] = (__float_as_uint(hidden[i]) & ~3u) | 0u;
    // slot 1 prefill: tag 2 (never matches iter-1's expected tag 1)
    g_hx[1][i] = 2u;
}

// --------------------------------------------------- generic NT fp32 GEMM --
// C[m][n] = sum_k A[m][k] * B[n][k] + bias[n]   (used for the fc layer)
__global__ void gemm_nt_bias(const float* __restrict__ A,
                             const float* __restrict__ B,
                             const float* __restrict__ bias,
                             float* __restrict__ C,
                             int M, int N, int K) {
    __shared__ float As[16][65];
    __shared__ float Bs[16][65];
    const int tid = threadIdx.x;
    const int bx = blockIdx.x;
    const int by = blockIdx.y;
    const int tm = (tid >> 4) << 2;
    const int tn = (tid & 15) << 2;
    const int lr = tid >> 2;
    const int lk = (tid & 3) << 2;

    const float* Ap = A + (size_t)(by * 64 + lr) * K + lk;
    const float* Bp = B + (size_t)(bx * 64 + lr) * K + lk;

    float acc[4][4] = {};

    for (int k0 = 0; k0 < K; k0 += 16) {
        float4 av = *(const float4*)(Ap + k0);
        float4 bv = *(const float4*)(Bp + k0);
        As[lk + 0][lr] = av.x; As[lk + 1][lr] = av.y;
        As[lk + 2][lr] = av.z; As[lk + 3][lr] = av.w;
        Bs[lk + 0][lr] = bv.x; Bs[lk + 1][lr] = bv.y;
        Bs[lk + 2][lr] = bv.z; Bs[lk + 3][lr] = bv.w;
        __syncthreads();
#pragma unroll
        for (int k = 0; k < 16; k++) {
            float ra[4], rb[4];
#pragma unroll
            for (int i = 0; i < 4; i++) ra[i] = As[k][tm + i];
#pragma unroll
            for (int j = 0; j < 4; j++) rb[j] = Bs[k][tn + j];
#pragma unroll
            for (int i = 0; i < 4; i++)
#pragma unroll
                for (int j = 0; j < 4; j++)
                    acc[i][j] += ra[i] * rb[j];
        }
        __syncthreads();
    }

    float bb[4];
#pragma unroll
    for (int j = 0; j < 4; j++) bb[j] = bias[bx * 64 + tn + j];
#pragma unroll
    for (int i = 0; i < 4; i++) {
        int row = by * 64 + tm + i;
        float* cp = C + (size_t)row * N + bx * 64 + tn;
#pragma unroll
        for (int j = 0; j < 4; j++) cp[j] = acc[i][j] + bb[j];
    }
}

// ------------- fused scan: R11 consumer warps + xh producer warps ----------
// Warps 0-7  (256 thr): R11 tagged-staging scan, barriers via bar.sync 1.
// Warps 8-15 (256 thr): compute xh rows bid*8..+7 for all t (GEMM1 strip),
//   input staged 8 rows/round via smem (bar.sync 2), Wxh row in registers,
//   publishing tagged xh words ~16x ahead of the scan's consumption.
__global__ void __launch_bounds__(SCAN_T, 1)
scan_kernel(const float* __restrict__ Whh,
            const float* __restrict__ input,
            const float* __restrict__ Wxh,
            const float* __restrict__ wxb,
            const float* __restrict__ whb,
            const float* __restrict__ bh) {
    const int bid  = blockIdx.x;
    const int tid  = threadIdx.x;
    const int wid  = tid >> 5;
    const int lane = tid & 31;

    __shared__ float    hs[HID];
    __shared__ unsigned hout[8];             // tagged h_{t+1} of this block
    __shared__ float4   ibuf[8 * IN_DIM / 4];// 16KB input stage (8 t-rows)

    if (wid >= 8) {
        // ================= xh producer =================
        const int g    = wid - 8;            // 0..7
        const int r    = bid * 8 + g;        // my output row
        const int ptid = tid - 256;          // 0..255 within producer group

        const float* wrow = Wxh + (size_t)r * IN_DIM + lane * 16;
        float4 w0 = *(const float4*)(wrow + 0);
        float4 w1 = *(const float4*)(wrow + 4);
        float4 w2 = *(const float4*)(wrow + 8);
        float4 w3 = *(const float4*)(wrow + 12);
        const float bias = wxb[r] + whb[r] + bh[r];
        unsigned* dst = g_xh + r;

#pragma unroll 1
        for (int t0 = 0; t0 < SEQ; t0 += 8) {
            // cooperative stage of input[t0..t0+7][:] (contiguous 16KB)
            const float4* src = (const float4*)(input + (size_t)t0 * IN_DIM);
#pragma unroll
            for (int i = 0; i < 4; i++)
                ibuf[ptid + i * 256] = src[ptid + i * 256];
            BAR_PROD();

#pragma unroll 1
            for (int u = 0; u < 8; u++) {
                const float4* ip = ibuf + u * (IN_DIM / 4) + lane * 4;
                float4 i0 = ip[0], i1 = ip[1], i2 = ip[2], i3 = ip[3];
                float s0 = w0.x*i0.x + w0.y*i0.y + w0.z*i0.z + w0.w*i0.w;
                float s1 = w1.x*i1.x + w1.y*i1.y + w1.z*i1.z + w1.w*i1.w;
                float s2 = w2.x*i2.x + w2.y*i2.y + w2.z*i2.z + w2.w*i2.w;
                float s3 = w3.x*i3.x + w3.y*i3.y + w3.z*i3.z + w3.w*i3.w;
                float s = (s0 + s1) + (s2 + s3);
#pragma unroll
                for (int o = 16; o > 0; o >>= 1)
                    s += __shfl_xor_sync(0xFFFFFFFFu, s, o);
                if (lane == 0) {
                    unsigned wb = (__float_as_uint(s + bias) & ~3u) | 1u;
                    st_relaxed_u32(dst + (size_t)(t0 + u) * HID, wb);
                }
            }
            BAR_PROD();                      // ibuf consumed before refill
        }
        return;
    }

    // ================= scan consumer (R11 body, named barriers) ============
    const int row = bid * 8 + wid;           // my warp's hidden row

    // Whh row slice in registers: w4[k] = Whh[row][k*128 + lane*4 .. +3]
    float4 w4[8];
#pragma unroll
    for (int k = 0; k < 8; k++)
        w4[k] = *(const float4*)&Whh[(size_t)row * HID + k * 128 + lane * 4];

    // xh pipeline (lane 0 of each warp), depth 2 — tag-polled
    float xh_c = 0.f, xh_n = 0.f;
    if (lane == 0) {
        xh_c = poll_xh(g_xh + row);
        xh_n = poll_xh(g_xh + (size_t)HID + row);
    }

#pragma unroll 1
    for (int t = 0; t < SEQ; t++) {
        // ---- fused poll+stage: my 16B of h_t, tag-validated ----
        {
            const unsigned* p = g_hx[t & 1] + tid * 4;
            const unsigned  tg = (unsigned)(t & 3);
            uint4 u = ld_relaxed_v4(p);
            while (!TAGOK(u, tg))
                u = ld_relaxed_v4(p);
            *(uint4*)&((unsigned*)hs)[tid * 4] = u;
        }
        BAR_SCAN();

        // ---- MV: acc = Whh[row] . h_t  (8 x LDS.128) ----
        float a0 = 0.f, a1 = 0.f, a2 = 0.f, a3 = 0.f;
#pragma unroll
        for (int k = 0; k < 8; k++) {
            float4 hv = *(const float4*)&hs[k * 128 + lane * 4];
            a0 = fmaf(w4[k].x, hv.x, a0);
            a1 = fmaf(w4[k].y, hv.y, a1);
            a2 = fmaf(w4[k].z, hv.z, a2);
            a3 = fmaf(w4[k].w, hv.w, a3);
        }
        float acc = (a0 + a1) + (a2 + a3);
#pragma unroll
        for (int o = 16; o > 0; o >>= 1)
            acc += __shfl_xor_sync(0xFFFFFFFFu, acc, o);

        if (lane == 0) {
            float hn = fast_tanh(xh_c + acc);
            unsigned nb = (__float_as_uint(hn) & ~3u) |
                          (unsigned)((t + 1) & 3);
            hout[wid] = nb;                               // stage for publish
            g_outs[(size_t)t * HID + row] = __uint_as_float(nb);
        }
        BAR_SCAN();            // hout complete; hs fully consumed

        // ---- aggregated publish: two 16B stores cover the block's 8 rows --
        if (tid < 2)
            st_relaxed_v4(&g_hx[(t + 1) & 1][bid * 8 + tid * 4],
                          *(const uint4*)&hout[tid * 4]);

        // ---- rotate xh pipeline AFTER publish (poll is off-chain) ----
        if (lane == 0) {
            xh_c = xh_n;
            xh_n = (t + 2 < SEQ)
                 ? poll_xh(g_xh + (size_t)(t + 2) * HID + row) : 0.f;
        }
    }
}

// ----------------------------------------------------------- row softmax ---
__global__ void softmax256(float* __restrict__ X) {
    const int r = blockIdx.x;
    const int tid = threadIdx.x;          // 256
    const int wid = tid >> 5, lane = tid & 31;
    __shared__ float red[8];

    float v = X[(size_t)r * OUT_DIM + tid];

    float m = v;
#pragma unroll
    for (int o = 16; o > 0; o >>= 1)
        m = fmaxf(m, __shfl_xor_sync(0xFFFFFFFFu, m, o));
    if (lane == 0) red[wid] = m;
    __syncthreads();
    if (tid == 0) {
        float mm = red[0];
#pragma unroll
        for (int i = 1; i < 8; i++) mm = fmaxf(mm, red[i]);
        red[0] = mm;
    }
    __syncthreads();
    const float bm = red[0];
    __syncthreads();

    float e = expf(v - bm);
    float s = e;
#pragma unroll
    for (int o = 16; o > 0; o >>= 1)
        s += __shfl_xor_sync(0xFFFFFFFFu, s, o);
    if (lane == 0) red[wid] = s;
    __syncthreads();
    if (tid == 0) {
        float ss = red[0];
#pragma unroll
        for (int i = 1; i < 8; i++) ss += red[i];
        red[0] = ss;
    }
    __syncthreads();
    X[(size_t)r * OUT_DIM + tid] = e / red[0];
}

// ------------------------------------------------------------------ launch -
extern "C" void kernel_launch(void* const* d_in, const int* in_sizes, int n_in,
                              void* d_out, int out_size) {
    const float* input  = (const float*)d_in[0];   // (SEQ, IN)
    const float* hidden = (const float*)d_in[1];   // (HID,)
    const float* Wxh_w  = (const float*)d_in[2];   // (HID, IN)
    const float* Wxh_b  = (const float*)d_in[3];   // (HID,)
    const float* Whh_w  = (const float*)d_in[4];   // (HID, HID)
    const float* Whh_b  = (const float*)d_in[5];   // (HID,)
    const float* bh     = (const float*)d_in[6];   // (HID,)
    const float* fc_w   = (const float*)d_in[7];   // (OUT, HID)
    const float* fc_b   = (const float*)d_in[8];   // (OUT,)
    float* out = (float*)d_out;                    // (SEQ, OUT)

    float* outs_ptr = nullptr;
    cudaGetSymbolAddress((void**)&outs_ptr, g_outs);

    // 0) seed tagged h exchange slots (every launch => replay-safe)
    reset_kernel<<<1, HID>>>(hidden);

    // 1+2) fused: xh production (hidden) + sequential recurrence
    scan_kernel<<<NB, SCAN_T>>>(Whh_w, input, Wxh_w, Wxh_b, Whh_b, bh);

    // 3) logits = outs @ fc_w.T + fc_b    (M=SEQ, N=OUT, K=HID) -> d_out
    {
        dim3 grid(OUT_DIM / 64, SEQ / 64);
        gemm_nt_bias<<<grid, 256>>>(outs_ptr, fc_w, fc_b, out,
                                    SEQ, OUT_DIM, HID);
    }

    // 4) softmax rows in place on d_out
    softmax256<<<SEQ, OUT_DIM>>>(out);
}